// round 15
// baseline (speedup 1.0000x reference)
#include <cuda_runtime.h>
#include <math.h>

#define HW (1024 * 1024)
#define NPIX4 (HW / 4)          // 262144 float4 per plane
#define SBLK  512               // blocks for k_fused (256 thr, 8 px/thread)
#define NGRAD_SM 258            // per-block gradients: sum 2*(RES+1)

// Scratch (allocation-free: __device__ globals)
__device__ float  g_bmn[5][SBLK];   // per-block partial minima (rewritten each run)
__device__ float  g_bmx[5][SBLK];   // per-block partial maxima
__device__ float  g_snorm[5];       // final per-octave scale (2*amp*mix/(mx-mn))
__device__ float  g_bpart[5];       // final per-octave bias part
__device__ float4 g_noise4[NPIX4];  // final noise, pre-multiplied by mix
__device__ unsigned g_tick = 0;     // last-block ticket (self-resetting)
__device__ unsigned g_rel  = 0;     // MONOTONIC release counter (never reset)

// ---------------------------------------------------------------------------
// Perlin per-cell-row constants.  For fixed row i and cell containing j0:
//   n(j) = t0 + wx*t1,  t0 = C0 + P1*D0,  t1 = E + P1*F
// Gradients come from block-shared memory (2 rows x (RES+1) per octave).
// smem layout offsets (float2 units): O0:0  O1:10  O2:28  O3:62  O4:128
// ---------------------------------------------------------------------------
struct RunConst { float C0, D0, E, F; };

template <int O>
__device__ __forceinline__ RunConst run_const_sm(const float2* sg, int i, int j0) {
    constexpr int RES = 4 << O;
    constexpr int SH  = 8 - O;
    constexpr int SOFF[5] = {0, 10, 28, 62, 128};
    const float delta = (float)RES / 1023.0f;

    float vy = (float)i * delta;
    float P0 = vy - floorf(vy);
    float wy = P0 * P0 * (3.0f - 2.0f * P0);

    int cx = j0 >> SH;
    const float2* g = sg + SOFF[O];
    float2 g00 = g[cx];
    float2 g10 = g[(RES + 1) + cx];
    float2 g01 = g[cx + 1];
    float2 g11 = g[(RES + 1) + cx + 1];

    float A0 = P0 * g00.x;
    float A1 = (P0 - 1.0f) * g10.x;
    float B0 = P0 * g01.x - g01.y;
    float B1 = (P0 - 1.0f) * g11.x - g11.y;

    float C0 = A0 + wy * (A1 - A0);
    float D0 = g00.y + wy * (g10.y - g00.y);
    float C1 = B0 + wy * (B1 - B0);
    float D1 = g01.y + wy * (g11.y - g01.y);

    RunConst rc;
    rc.C0 = C0; rc.D0 = D0; rc.E = C1 - C0; rc.F = D1 - D0;
    return rc;
}

// ---------------------------------------------------------------------------
// Fill the block's gradient smem table: 2 rows x (RES+1) cos/sin per octave.
// Block covers rows i0, i0+1 (i0 even) -> one cell-row at every octave.
// Compile-time W per branch (mul-shift, no IDIV).  __sincosf: abs err ~5e-7.
// ---------------------------------------------------------------------------
#define FILL_BRANCH(o, BASE, W)                                         \
    {                                                                   \
        int local = idx - (BASE);                                       \
        int row = local / (W);                                          \
        int cx  = local - row * (W);                                    \
        int cy0 = i0 >> (8 - (o));                                      \
        float a = angs[o][(cy0 + row) * (W) + cx];                      \
        float s, c;                                                     \
        __sincosf(a, &s, &c);                                           \
        sg[idx] = make_float2(c, s);                                    \
    }

__device__ __forceinline__ void fill_grad_sm(
    float2* sg, int i0,
    const float* a0, const float* a1, const float* a2,
    const float* a3, const float* a4)
{
    const float* angs[5] = {a0, a1, a2, a3, a4};
#pragma unroll
    for (int rep = 0; rep < 2; rep++) {
        int idx = threadIdx.x + rep * 256;
        if      (idx < 10)       FILL_BRANCH(0, 0,   5)
        else if (idx < 28)       FILL_BRANCH(1, 10,  9)
        else if (idx < 62)       FILL_BRANCH(2, 28,  17)
        else if (idx < 128)      FILL_BRANCH(3, 62,  33)
        else if (idx < NGRAD_SM) FILL_BRANCH(4, 128, 65)
    }
}

// ---------------------------------------------------------------------------
// k_fused: noise + EXACT min/max + normalization publish, one kernel.
//   1. launch_dependents (apply prefetches image underneath)
//   2. fill gradients; compute exact unscaled per-pixel noise nv[8][5]
//   3. block min/max over OWN nv values (exact!) -> partials
//   4. atomic ticket: LAST block reduces 512 partials, publishes
//      g_snorm/g_bpart (mix folded), bumps monotonic g_rel
//   5. all blocks spin until release, then scale + store noise
// 512 blocks, __launch_bounds__(256,4) => <=64 regs => 592 slots >= 512:
// all blocks co-resident, spin is deadlock-free (proven R7-R10 config).
// ---------------------------------------------------------------------------
__global__ void __launch_bounds__(256, 4) k_fused(
    const float* __restrict__ a0, const float* __restrict__ a1,
    const float* __restrict__ a2, const float* __restrict__ a3,
    const float* __restrict__ a4, const float* __restrict__ mixp)
{
    asm volatile("griddepcontrol.launch_dependents;");

    __shared__ float2 sgrad[NGRAD_SM];
    __shared__ float smn[5][8], smx[5][8];
    __shared__ float ss[5], sB[5];
    __shared__ unsigned s_r0;
    __shared__ int s_last;

    if (threadIdx.x == 0) s_r0 = *((volatile unsigned*)&g_rel);

    int i0 = blockIdx.x * 2;
    fill_grad_sm(sgrad, i0, a0, a1, a2, a3, a4);
    __syncthreads();           // covers sgrad AND s_r0
    unsigned R0 = s_r0;

    int t = blockIdx.x * 256 + threadIdx.x;   // 0..131071
    int i  = t >> 7;
    int j0 = (t & 127) << 3;
    bool wrap = (j0 == 1016);

    RunConst r0 = run_const_sm<0>(sgrad, i, j0);
    RunConst r1 = run_const_sm<1>(sgrad, i, j0);
    RunConst r2 = run_const_sm<2>(sgrad, i, j0);
    RunConst r3 = run_const_sm<3>(sgrad, i, j0);
    RunConst r4 = run_const_sm<4>(sgrad, i, j0);

    // unscaled incremental state:
    //   t0_o(j) = C0 + P1*D0;  T1u_o(j) = E + P1*F;  step by dl per pixel
    const float dl[5] = {4.0f / 1023.0f, 8.0f / 1023.0f, 16.0f / 1023.0f,
                         32.0f / 1023.0f, 64.0f / 1023.0f};
    float P1[5], t0[5], dt0[5], T1u[5], dT1u[5];
#define INITO(o, rc)                                                    \
    {                                                                   \
        float vx = (float)j0 * dl[o];                                   \
        P1[o]   = vx - floorf(vx);                                      \
        t0[o]   = fmaf(P1[o], rc.D0, rc.C0);                            \
        dt0[o]  = dl[o] * rc.D0;                                        \
        T1u[o]  = fmaf(P1[o], rc.F, rc.E);                              \
        dT1u[o] = dl[o] * rc.F;                                         \
    }
    INITO(0, r0) INITO(1, r1) INITO(2, r2) INITO(3, r3) INITO(4, r4)
#undef INITO

    // ---- exact unscaled per-pixel noise ------------------------------------
    float nv[8][5];
#pragma unroll
    for (int k = 0; k < 8; k++) {
#pragma unroll
        for (int o = 0; o < 5; o++) {
            float u = P1[o] * P1[o];
            float v = fmaf(-2.0f, P1[o], 3.0f);
            nv[k][o] = fmaf(u * v, T1u[o], t0[o]);
        }
#pragma unroll
        for (int o = 0; o < 5; o++) {
            P1[o] += dl[o]; t0[o] += dt0[o]; T1u[o] += dT1u[o];
        }
    }
    if (wrap) {   // j=1023: P1 wraps to 0 at every octave -> n_o = C0_o
        nv[7][0] = r0.C0; nv[7][1] = r1.C0; nv[7][2] = r2.C0;
        nv[7][3] = r3.C0; nv[7][4] = r4.C0;
    }

    // ---- EXACT block min/max over own nv values ----------------------------
    float mn[5], mx[5];
#pragma unroll
    for (int o = 0; o < 5; o++) { mn[o] = nv[0][o]; mx[o] = nv[0][o]; }
#pragma unroll
    for (int k = 1; k < 8; k++) {
#pragma unroll
        for (int o = 0; o < 5; o++) {
            mn[o] = fminf(mn[o], nv[k][o]);
            mx[o] = fmaxf(mx[o], nv[k][o]);
        }
    }
#pragma unroll
    for (int o = 0; o < 5; o++) {
#pragma unroll
        for (int d = 16; d > 0; d >>= 1) {
            mn[o] = fminf(mn[o], __shfl_xor_sync(0xFFFFFFFFu, mn[o], d));
            mx[o] = fmaxf(mx[o], __shfl_xor_sync(0xFFFFFFFFu, mx[o], d));
        }
    }
    int w = threadIdx.x >> 5, lane = threadIdx.x & 31;
    if (lane == 0) {
#pragma unroll
        for (int o = 0; o < 5; o++) { smn[o][w] = mn[o]; smx[o][w] = mx[o]; }
    }
    __syncthreads();
    if (threadIdx.x < 5) {
        int o = threadIdx.x;
        float a = smn[o][0], b = smx[o][0];
#pragma unroll
        for (int k = 1; k < 8; k++) { a = fminf(a, smn[o][k]); b = fmaxf(b, smx[o][k]); }
        g_bmn[o][blockIdx.x] = a;
        g_bmx[o][blockIdx.x] = b;
    }

    // ---- ticket: last block reduces + publishes ----------------------------
    __threadfence();
    if (threadIdx.x == 0) {
        unsigned old = atomicAdd(&g_tick, 1);
        s_last = (old == SBLK - 1) ? 1 : 0;
        if (s_last) atomicExch(&g_tick, 0);   // reset for next replay
    }
    __syncthreads();
    if (s_last) {
        float pm[5], px[5];
#pragma unroll
        for (int o = 0; o < 5; o++) {
            pm[o] = fminf(__ldcg(&g_bmn[o][threadIdx.x]),
                          __ldcg(&g_bmn[o][threadIdx.x + 256]));
            px[o] = fmaxf(__ldcg(&g_bmx[o][threadIdx.x]),
                          __ldcg(&g_bmx[o][threadIdx.x + 256]));
        }
#pragma unroll
        for (int o = 0; o < 5; o++) {
#pragma unroll
            for (int d = 16; d > 0; d >>= 1) {
                pm[o] = fminf(pm[o], __shfl_xor_sync(0xFFFFFFFFu, pm[o], d));
                px[o] = fmaxf(px[o], __shfl_xor_sync(0xFFFFFFFFu, px[o], d));
            }
        }
        if (lane == 0) {
#pragma unroll
            for (int o = 0; o < 5; o++) { smn[o][w] = pm[o]; smx[o][w] = px[o]; }
        }
        __syncthreads();
        if (threadIdx.x < 5) {
            int o = threadIdx.x;
            float a = smn[o][0], b = smx[o][0];
#pragma unroll
            for (int k = 1; k < 8; k++) { a = fminf(a, smn[o][k]); b = fmaxf(b, smx[o][k]); }
            const float amps[5] = {0.1f, 0.05f, 0.025f, 0.0125f, 0.00625f};
            float inv = 1.0f / (b - a);
            float am = amps[o] * (*mixp);
            g_snorm[o] = 2.0f * am * inv;
            g_bpart[o] = am * (-2.0f * a * inv - 1.0f);
        }
        __syncthreads();
        if (threadIdx.x == 0) {
            __threadfence();
            atomicAdd(&g_rel, 1);   // release all blocks
        }
    }

    // ---- spin for release, then scale + store ------------------------------
    if (threadIdx.x == 0) {
        while (*((volatile unsigned*)&g_rel) < R0 + 1) { __nanosleep(32); }
        __threadfence();   // acquire
    }
    __syncthreads();

    if (threadIdx.x < 5) { ss[threadIdx.x] = __ldcg(&g_snorm[threadIdx.x]);
                           sB[threadIdx.x] = __ldcg(&g_bpart[threadIdx.x]); }
    __syncthreads();

    float s0 = ss[0], s1 = ss[1], s2 = ss[2], s3 = ss[3], s4 = ss[4];
    float B = sB[0] + sB[1] + sB[2] + sB[3] + sB[4];

    float vals[8];
#pragma unroll
    for (int k = 0; k < 8; k++) {
        float acc = B;
        acc = fmaf(s0, nv[k][0], acc);
        acc = fmaf(s1, nv[k][1], acc);
        acc = fmaf(s2, nv[k][2], acc);
        acc = fmaf(s3, nv[k][3], acc);
        acc = fmaf(s4, nv[k][4], acc);
        vals[k] = acc;
    }

    int p4 = t << 1;
    g_noise4[p4]     = make_float4(vals[0], vals[1], vals[2], vals[3]);
    g_noise4[p4 + 1] = make_float4(vals[4], vals[5], vals[6], vals[7]);
}

// ---------------------------------------------------------------------------
// k_apply (PDL-dependent on k_fused): HBM-bound streaming apply.
// Proven VPT=4 shape: img loads issued BEFORE griddepcontrol.wait;
// noise reads/stores after the wait.
// ---------------------------------------------------------------------------
#define VPT 4
__global__ void __launch_bounds__(256) k_apply(const float4* __restrict__ img,
                                               float4* __restrict__ out, int n4) {
    int base = blockIdx.x * (256 * VPT) + threadIdx.x;

    if (base + 3 * 256 < n4) {
        float4 v0 = __ldcs(img + base);
        float4 v1 = __ldcs(img + base + 256);
        float4 v2 = __ldcs(img + base + 512);
        float4 v3 = __ldcs(img + base + 768);

        asm volatile("griddepcontrol.wait;" ::: "memory");

        float4 n0 = g_noise4[(base)       & (NPIX4 - 1)];
        float4 n1 = g_noise4[(base + 256) & (NPIX4 - 1)];
        float4 n2 = g_noise4[(base + 512) & (NPIX4 - 1)];
        float4 n3 = g_noise4[(base + 768) & (NPIX4 - 1)];

        v0.x = fminf(fmaxf(v0.x + n0.x, 0.0f), 1.0f);
        v0.y = fminf(fmaxf(v0.y + n0.y, 0.0f), 1.0f);
        v0.z = fminf(fmaxf(v0.z + n0.z, 0.0f), 1.0f);
        v0.w = fminf(fmaxf(v0.w + n0.w, 0.0f), 1.0f);
        v1.x = fminf(fmaxf(v1.x + n1.x, 0.0f), 1.0f);
        v1.y = fminf(fmaxf(v1.y + n1.y, 0.0f), 1.0f);
        v1.z = fminf(fmaxf(v1.z + n1.z, 0.0f), 1.0f);
        v1.w = fminf(fmaxf(v1.w + n1.w, 0.0f), 1.0f);
        v2.x = fminf(fmaxf(v2.x + n2.x, 0.0f), 1.0f);
        v2.y = fminf(fmaxf(v2.y + n2.y, 0.0f), 1.0f);
        v2.z = fminf(fmaxf(v2.z + n2.z, 0.0f), 1.0f);
        v2.w = fminf(fmaxf(v2.w + n2.w, 0.0f), 1.0f);
        v3.x = fminf(fmaxf(v3.x + n3.x, 0.0f), 1.0f);
        v3.y = fminf(fmaxf(v3.y + n3.y, 0.0f), 1.0f);
        v3.z = fminf(fmaxf(v3.z + n3.z, 0.0f), 1.0f);
        v3.w = fminf(fmaxf(v3.w + n3.w, 0.0f), 1.0f);

        __stcs(out + base,       v0);
        __stcs(out + base + 256, v1);
        __stcs(out + base + 512, v2);
        __stcs(out + base + 768, v3);
    } else {
        asm volatile("griddepcontrol.wait;" ::: "memory");
        for (int k = 0; k < VPT; k++) {
            int idx = base + k * 256;
            if (idx >= n4) break;
            float4 nz = g_noise4[idx & (NPIX4 - 1)];
            float4 v = __ldcs(img + idx);
            v.x = fminf(fmaxf(v.x + nz.x, 0.0f), 1.0f);
            v.y = fminf(fmaxf(v.y + nz.y, 0.0f), 1.0f);
            v.z = fminf(fmaxf(v.z + nz.z, 0.0f), 1.0f);
            v.w = fminf(fmaxf(v.w + nz.w, 0.0f), 1.0f);
            __stcs(out + idx, v);
        }
    }
}

// ---------------------------------------------------------------------------
extern "C" void kernel_launch(void* const* d_in, const int* in_sizes, int n_in,
                              void* d_out, int out_size) {
    const float* image = nullptr;
    const float* mixp  = nullptr;
    const float* ang[5] = {nullptr, nullptr, nullptr, nullptr, nullptr};

    for (int k = 0; k < n_in; k++) {
        int s = in_sizes[k];
        const float* p = (const float*)d_in[k];
        if      (s == 1)    mixp   = p;
        else if (s == 25)   ang[0] = p;
        else if (s == 81)   ang[1] = p;
        else if (s == 289)  ang[2] = p;
        else if (s == 1089) ang[3] = p;
        else if (s == 4225) ang[4] = p;
        else                image  = p;   // 16*3*1024*1024
    }

    int n4 = out_size / 4;
    unsigned ablocks = (unsigned)((n4 + 256 * VPT - 1) / (256 * VPT));

    // K1: fused noise + exact min/max + publish (plain launch)
    k_fused<<<SBLK, 256>>>(ang[0], ang[1], ang[2], ang[3], ang[4], mixp);

    // K2: PDL-dependent apply (img prefetch overlaps k_fused)
    cudaLaunchAttribute attrs[1];
    attrs[0].id = cudaLaunchAttributeProgrammaticStreamSerialization;
    attrs[0].val.programmaticStreamSerializationAllowed = 1;

    cudaLaunchConfig_t cfg = {};
    cfg.gridDim  = dim3(ablocks, 1, 1);
    cfg.blockDim = dim3(256, 1, 1);
    cfg.attrs = attrs;
    cfg.numAttrs = 1;
    cudaError_t e = cudaLaunchKernelEx(&cfg, k_apply,
                                       (const float4*)image, (float4*)d_out, n4);
    if (e != cudaSuccess) {
        k_apply<<<ablocks, 256>>>((const float4*)image, (float4*)d_out, n4);
    }
}